// round 1
// baseline (speedup 1.0000x reference)
#include <cuda_runtime.h>
#include <math.h>

// Problem constants
#define BB    512     // batch
#define LL    100     // tokens
#define MM    10      // negatives
#define DD    256     // embed dim
#define NASP  14      // aspects
#define BT    8       // batch tile for My GEMM

// Output layout: r_s [512,256] | z_s [512,256] | z_n [512,10,256]
#define OFF_RS  0
#define OFF_ZS  (BB*DD)            // 131072
#define OFF_ZN  (2*BB*DD)          // 262144

// Scratch (device globals — no allocations allowed)
__device__ float g_ys[BB*DD];
__device__ float g_My[BB*DD];

__device__ __forceinline__ float blockReduce256(float v, float* sh8) {
    #pragma unroll
    for (int o = 16; o > 0; o >>= 1) v += __shfl_xor_sync(0xffffffffu, v, o);
    int w = threadIdx.x >> 5;
    if ((threadIdx.x & 31) == 0) sh8[w] = v;
    __syncthreads();
    if (threadIdx.x < 8) {
        v = sh8[threadIdx.x];
        #pragma unroll
        for (int o = 4; o > 0; o >>= 1) v += __shfl_xor_sync(0xffu, v, o);
        if (threadIdx.x == 0) sh8[0] = v;
    }
    __syncthreads();
    return sh8[0];
}

// K1: blocks [0,512): y_s[b] = mean_l E_w[pos[b,l]]   (store to g_ys)
//     blocks [512,5632): z_n[b,m] = l2norm(mean_l E_w[negs[b,m,l]]) (write out)
__global__ void k_means(const int* __restrict__ pos, const int* __restrict__ negs,
                        const float* __restrict__ E_w, float* __restrict__ out)
{
    __shared__ int idx[LL];
    __shared__ float sh8[8];
    const int t = threadIdx.x;
    const int blk = blockIdx.x;
    const int* src = (blk < BB) ? (pos + blk * LL) : (negs + (blk - BB) * LL);
    if (t < LL) idx[t] = src[t];
    __syncthreads();

    float acc = 0.f;
    #pragma unroll 4
    for (int l = 0; l < LL; l++) {
        acc += E_w[(size_t)idx[l] * DD + t];
    }
    acc *= (1.0f / LL);

    if (blk < BB) {
        g_ys[blk * DD + t] = acc;
    } else {
        float ss = blockReduce256(acc * acc, sh8);
        float nrm = fmaxf(sqrtf(ss), 1e-12f);
        out[OFF_ZN + (blk - BB) * DD + t] = acc / nrm;
    }
}

// K2: My[b] = M_w @ y_s[b] + M_b, tiled 8 batch rows per block.
__global__ void k_my(const float* __restrict__ Mw, const float* __restrict__ Mb)
{
    __shared__ float ys[BT][DD];
    const int t = threadIdx.x;
    const int b0 = blockIdx.x * BT;
    #pragma unroll
    for (int i = 0; i < BT; i++) ys[i][t] = g_ys[(b0 + i) * DD + t];
    __syncthreads();

    const float* mr = Mw + t * DD;   // row t of M_w (thread-private, L1-reused)
    float acc[BT];
    #pragma unroll
    for (int i = 0; i < BT; i++) acc[i] = 0.f;
    #pragma unroll 4
    for (int d = 0; d < DD; d++) {
        float w = mr[d];
        #pragma unroll
        for (int i = 0; i < BT; i++) acc[i] += w * ys[i][d];
    }
    float bb = Mb[t];
    #pragma unroll
    for (int i = 0; i < BT; i++) g_My[(b0 + i) * DD + t] = acc[i] + bb;
}

// K3: per b: w_l = exp(tanh(e_l . My)); z_s = l2norm(sum_l w_l * e_l).
// (Global softmax denominator cancels under l2norm.)
__global__ void k_attn(const int* __restrict__ pos, const float* __restrict__ E_w,
                       float* __restrict__ out)
{
    __shared__ int idx[LL];
    __shared__ float My_s[DD];
    __shared__ float wgt[LL];
    __shared__ float sh8[8];
    const int t = threadIdx.x;
    const int b = blockIdx.x;
    if (t < LL) idx[t] = pos[b * LL + t];
    My_s[t] = g_My[b * DD + t];
    __syncthreads();

    const int w = t >> 5, ln = t & 31;
    for (int l = w; l < LL; l += 8) {
        const float* er = E_w + (size_t)idx[l] * DD;
        float p = 0.f;
        #pragma unroll
        for (int k = 0; k < 8; k++) p += er[ln + 32 * k] * My_s[ln + 32 * k];
        #pragma unroll
        for (int o = 16; o > 0; o >>= 1) p += __shfl_xor_sync(0xffffffffu, p, o);
        if (ln == 0) wgt[l] = expf(tanhf(p));
    }
    __syncthreads();

    float acc = 0.f;
    #pragma unroll 4
    for (int l = 0; l < LL; l++) acc += wgt[l] * E_w[(size_t)idx[l] * DD + t];

    float ss = blockReduce256(acc * acc, sh8);
    float nrm = fmaxf(sqrtf(ss), 1e-12f);
    out[OFF_ZS + b * DD + t] = acc / nrm;
}

// K4: p_t = softmax(z_s @ lin_w^T + lin_b); r_s = l2norm(p_t @ T_w)
__global__ void k_asp(const float* __restrict__ Tw, const float* __restrict__ lw,
                      const float* __restrict__ lb, float* __restrict__ out)
{
    __shared__ float zs[DD];
    __shared__ float lg[NASP];
    __shared__ float ps[NASP];
    __shared__ float sh8[8];
    const int t = threadIdx.x;
    const int b = blockIdx.x;
    zs[t] = out[OFF_ZS + b * DD + t];
    __syncthreads();

    const int w = t >> 5, ln = t & 31;
    for (int a = w; a < NASP; a += 8) {
        const float* lr = lw + a * DD;
        float p = 0.f;
        #pragma unroll
        for (int k = 0; k < 8; k++) p += lr[ln + 32 * k] * zs[ln + 32 * k];
        #pragma unroll
        for (int o = 16; o > 0; o >>= 1) p += __shfl_xor_sync(0xffffffffu, p, o);
        if (ln == 0) lg[a] = p + lb[a];
    }
    __syncthreads();

    if (t == 0) {
        float mx = -1e30f;
        #pragma unroll
        for (int a = 0; a < NASP; a++) mx = fmaxf(mx, lg[a]);
        float s = 0.f;
        #pragma unroll
        for (int a = 0; a < NASP; a++) { float e = expf(lg[a] - mx); ps[a] = e; s += e; }
        float inv = 1.f / s;
        #pragma unroll
        for (int a = 0; a < NASP; a++) ps[a] *= inv;
    }
    __syncthreads();

    float r = 0.f;
    #pragma unroll
    for (int a = 0; a < NASP; a++) r += ps[a] * Tw[a * DD + t];

    float ss = blockReduce256(r * r, sh8);
    float nrm = fmaxf(sqrtf(ss), 1e-12f);
    out[OFF_RS + b * DD + t] = r / nrm;
}

extern "C" void kernel_launch(void* const* d_in, const int* in_sizes, int n_in,
                              void* d_out, int out_size)
{
    const int*   pos  = (const int*)d_in[0];
    const int*   negs = (const int*)d_in[1];
    const float* E_w  = (const float*)d_in[2];
    const float* T_w  = (const float*)d_in[3];
    const float* M_w  = (const float*)d_in[4];
    const float* M_b  = (const float*)d_in[5];
    const float* lw   = (const float*)d_in[6];
    const float* lb   = (const float*)d_in[7];
    float* out = (float*)d_out;

    k_means<<<BB + BB * MM, DD>>>(pos, negs, E_w, out);
    k_my<<<BB / BT, DD>>>(M_w, M_b);
    k_attn<<<BB, DD>>>(pos, E_w, out);
    k_asp<<<BB, DD>>>(T_w, lw, lb, out);
}

// round 2
// speedup vs baseline: 1.4481x; 1.4481x over previous
#include <cuda_runtime.h>
#include <math.h>

#define BB    512
#define LL    100
#define MM    10
#define DD    256
#define NASP  14
#define BT    8

// Output layout: r_s [512,256] | z_s [512,256] | z_n [512,10,256]
#define OFF_RS  0
#define OFF_ZS  (BB*DD)
#define OFF_ZN  (2*BB*DD)

__device__ float g_ys[BB*DD];
__device__ float g_My[BB*DD];

__device__ __forceinline__ float blockReduce256(float v, float* sh8) {
    #pragma unroll
    for (int o = 16; o > 0; o >>= 1) v += __shfl_xor_sync(0xffffffffu, v, o);
    int w = threadIdx.x >> 5;
    if ((threadIdx.x & 31) == 0) sh8[w] = v;
    __syncthreads();
    if (threadIdx.x < 8) {
        v = sh8[threadIdx.x];
        #pragma unroll
        for (int o = 4; o > 0; o >>= 1) v += __shfl_xor_sync(0xffu, v, o);
        if (threadIdx.x == 0) sh8[0] = v;
    }
    __syncthreads();
    return sh8[0];
}

// ---------------------------------------------------------------------------
// K1: y_s[b] = mean_l E_w[pos[b,l]]  (float4-vectorized gather)
// thread t: r = t>>6 (row-phase 0..3), c = t&63 (float4 column)
// ---------------------------------------------------------------------------
__global__ __launch_bounds__(256) void k_posmean(
    const int* __restrict__ pos, const float4* __restrict__ E4)
{
    __shared__ int idx[LL];
    __shared__ float4 red[256];
    const int t = threadIdx.x, b = blockIdx.x;
    if (t < LL) idx[t] = pos[b * LL + t];
    __syncthreads();

    const int r = t >> 6, c = t & 63;
    float4 a = make_float4(0.f, 0.f, 0.f, 0.f);
    #pragma unroll 5
    for (int i = 0; i < LL / 4; i++) {
        float4 v = E4[(size_t)idx[i * 4 + r] * 64 + c];
        a.x += v.x; a.y += v.y; a.z += v.z; a.w += v.w;
    }
    red[t] = a;
    __syncthreads();
    if (t < 64) {
        float4 s = red[t], p1 = red[t+64], p2 = red[t+128], p3 = red[t+192];
        s.x = (s.x+p1.x+p2.x+p3.x) * (1.f/LL);
        s.y = (s.y+p1.y+p2.y+p3.y) * (1.f/LL);
        s.z = (s.z+p1.z+p2.z+p3.z) * (1.f/LL);
        s.w = (s.w+p1.w+p2.w+p3.w) * (1.f/LL);
        ((float4*)g_ys)[b * 64 + t] = s;
    }
}

// ---------------------------------------------------------------------------
// K2: My[b] = M_w @ y_s[b] + M_b   (8 batch rows per block)
// ---------------------------------------------------------------------------
__global__ __launch_bounds__(256) void k_my(
    const float* __restrict__ Mw, const float* __restrict__ Mb)
{
    __shared__ float ys[BT][DD];
    const int t = threadIdx.x;
    const int b0 = blockIdx.x * BT;
    #pragma unroll
    for (int i = 0; i < BT; i++) ys[i][t] = g_ys[(b0 + i) * DD + t];
    __syncthreads();

    const float* mr = Mw + t * DD;
    float acc[BT];
    #pragma unroll
    for (int i = 0; i < BT; i++) acc[i] = 0.f;
    #pragma unroll 4
    for (int d = 0; d < DD; d++) {
        float w = mr[d];
        #pragma unroll
        for (int i = 0; i < BT; i++) acc[i] += w * ys[i][d];
    }
    float bb = Mb[t];
    #pragma unroll
    for (int i = 0; i < BT; i++) g_My[(b0 + i) * DD + t] = acc[i] + bb;
}

// ---------------------------------------------------------------------------
// K3 fused:
//   blocks [0,512):   attention -> z_s, then aspect head -> r_s  (block-local)
//   blocks [512,5632): z_n[b,m] = l2norm(sum_l E_w[negs[...]])  (mean scale
//                      cancels under l2norm)
// ---------------------------------------------------------------------------
__global__ __launch_bounds__(256) void k_fused(
    const int* __restrict__ pos, const int* __restrict__ negs,
    const float4* __restrict__ E4,
    const float* __restrict__ Tw, const float* __restrict__ lw,
    const float* __restrict__ lb, float* __restrict__ out)
{
    __shared__ int idx[LL];
    __shared__ float4 red[256];
    __shared__ float sh8[8];
    const int t = threadIdx.x, blk = blockIdx.x;
    const int r = t >> 6, c = t & 63;
    const int wid = t >> 5, lane = t & 31;

    if (blk >= BB) {
        // ---- negatives mean + l2norm ----
        const int bm = blk - BB;
        if (t < LL) idx[t] = negs[bm * LL + t];
        __syncthreads();
        float4 a = make_float4(0.f, 0.f, 0.f, 0.f);
        #pragma unroll 5
        for (int i = 0; i < LL / 4; i++) {
            float4 v = E4[(size_t)idx[i * 4 + r] * 64 + c];
            a.x += v.x; a.y += v.y; a.z += v.z; a.w += v.w;
        }
        red[t] = a;
        __syncthreads();
        if (t < 64) {
            float4 s = red[t], p1 = red[t+64], p2 = red[t+128], p3 = red[t+192];
            s.x += p1.x+p2.x+p3.x; s.y += p1.y+p2.y+p3.y;
            s.z += p1.z+p2.z+p3.z; s.w += p1.w+p2.w+p3.w;
            red[t] = s;
            float ss = s.x*s.x + s.y*s.y + s.z*s.z + s.w*s.w;
            #pragma unroll
            for (int o = 16; o > 0; o >>= 1) ss += __shfl_xor_sync(0xffffffffu, ss, o);
            if (lane == 0) sh8[wid] = ss;
        }
        __syncthreads();
        if (t < 64) {
            float inv = 1.f / fmaxf(sqrtf(sh8[0] + sh8[1]), 1e-12f);
            float4 s = red[t];
            s.x *= inv; s.y *= inv; s.z *= inv; s.w *= inv;
            ((float4*)(out + OFF_ZN))[bm * 64 + t] = s;
        }
        return;
    }

    // ---- attention + aspect head for b = blk ----
    __shared__ float Mys[DD];
    __shared__ float wgt[LL];
    __shared__ float zs[DD];
    __shared__ float lg[NASP];
    __shared__ float ps[NASP];
    const int b = blk;
    if (t < LL) idx[t] = pos[b * LL + t];
    Mys[t] = g_My[b * DD + t];
    __syncthreads();

    // per-token weights: w_l = exp(tanh(e_l . My))  (warp per token)
    for (int l = wid; l < LL; l += 8) {
        const float4* er = E4 + (size_t)idx[l] * 64;
        float4 v1 = er[lane], v2 = er[lane + 32];
        float p = v1.x * Mys[4*lane+0] + v1.y * Mys[4*lane+1]
                + v1.z * Mys[4*lane+2] + v1.w * Mys[4*lane+3]
                + v2.x * Mys[128+4*lane+0] + v2.y * Mys[128+4*lane+1]
                + v2.z * Mys[128+4*lane+2] + v2.w * Mys[128+4*lane+3];
        #pragma unroll
        for (int o = 16; o > 0; o >>= 1) p += __shfl_xor_sync(0xffffffffu, p, o);
        if (lane == 0) wgt[l] = expf(tanhf(p));
    }
    __syncthreads();

    // weighted sum (global softmax denom cancels under l2norm)
    float4 a = make_float4(0.f, 0.f, 0.f, 0.f);
    #pragma unroll 5
    for (int i = 0; i < LL / 4; i++) {
        const int l = i * 4 + r;
        const float w = wgt[l];
        float4 v = E4[(size_t)idx[l] * 64 + c];
        a.x += w * v.x; a.y += w * v.y; a.z += w * v.z; a.w += w * v.w;
    }
    red[t] = a;
    __syncthreads();
    if (t < 64) {
        float4 s = red[t], p1 = red[t+64], p2 = red[t+128], p3 = red[t+192];
        s.x += p1.x+p2.x+p3.x; s.y += p1.y+p2.y+p3.y;
        s.z += p1.z+p2.z+p3.z; s.w += p1.w+p2.w+p3.w;
        red[t] = s;
        float ss = s.x*s.x + s.y*s.y + s.z*s.z + s.w*s.w;
        #pragma unroll
        for (int o = 16; o > 0; o >>= 1) ss += __shfl_xor_sync(0xffffffffu, ss, o);
        if (lane == 0) sh8[wid] = ss;
    }
    __syncthreads();
    if (t < 64) {
        float inv = 1.f / fmaxf(sqrtf(sh8[0] + sh8[1]), 1e-12f);
        float4 s = red[t];
        s.x *= inv; s.y *= inv; s.z *= inv; s.w *= inv;
        ((float4*)zs)[t] = s;
        ((float4*)(out + OFF_ZS))[b * 64 + t] = s;
    }
    __syncthreads();

    // logits over 14 aspects (warp per aspect)
    for (int asp = wid; asp < NASP; asp += 8) {
        const float4* lr = (const float4*)(lw + asp * DD);
        float4 v1 = lr[lane], v2 = lr[lane + 32];
        float p = v1.x * zs[4*lane+0] + v1.y * zs[4*lane+1]
                + v1.z * zs[4*lane+2] + v1.w * zs[4*lane+3]
                + v2.x * zs[128+4*lane+0] + v2.y * zs[128+4*lane+1]
                + v2.z * zs[128+4*lane+2] + v2.w * zs[128+4*lane+3];
        #pragma unroll
        for (int o = 16; o > 0; o >>= 1) p += __shfl_xor_sync(0xffffffffu, p, o);
        if (lane == 0) lg[asp] = p + lb[asp];
    }
    __syncthreads();

    if (t == 0) {
        float mx = -1e30f;
        #pragma unroll
        for (int aa = 0; aa < NASP; aa++) mx = fmaxf(mx, lg[aa]);
        float s = 0.f;
        #pragma unroll
        for (int aa = 0; aa < NASP; aa++) { float e = expf(lg[aa] - mx); ps[aa] = e; s += e; }
        float inv = 1.f / s;
        #pragma unroll
        for (int aa = 0; aa < NASP; aa++) ps[aa] *= inv;
    }
    __syncthreads();

    float rr = 0.f;
    #pragma unroll
    for (int aa = 0; aa < NASP; aa++) rr += ps[aa] * Tw[aa * DD + t];

    float ss = blockReduce256(rr * rr, sh8);
    float nrm = fmaxf(sqrtf(ss), 1e-12f);
    out[OFF_RS + b * DD + t] = rr / nrm;
}

extern "C" void kernel_launch(void* const* d_in, const int* in_sizes, int n_in,
                              void* d_out, int out_size)
{
    const int*   pos  = (const int*)d_in[0];
    const int*   negs = (const int*)d_in[1];
    const float* E_w  = (const float*)d_in[2];
    const float* T_w  = (const float*)d_in[3];
    const float* M_w  = (const float*)d_in[4];
    const float* M_b  = (const float*)d_in[5];
    const float* lw   = (const float*)d_in[6];
    const float* lb   = (const float*)d_in[7];
    float* out = (float*)d_out;

    k_posmean<<<BB, DD>>>(pos, (const float4*)E_w);
    k_my<<<BB / BT, DD>>>(M_w, M_b);
    k_fused<<<BB + BB * MM, DD>>>(pos, negs, (const float4*)E_w,
                                  T_w, lw, lb, out);
}